// round 5
// baseline (speedup 1.0000x reference)
#include <cuda_runtime.h>
#include <cuda_bf16.h>
#include <cstdint>

// OptionAttentionSum: out[b,o] = (sum_w sum_l [doc[b,l]==opt[b,o,w]] * prob[b,l]) / #nonzero words
//
// R4: single-launch version of R3. Grid = B*S CTAs (4 segments/batch, 256 thr).
// Each CTA: prefetch its doc segment (int4+float4 per thread), build 2048-slot
// hash table of the <=50 option words, probe (batched LDS, ~branchless), write
// per-segment partials, and the LAST CTA per batch (atomic counter) reduces the
// S partials, divides by the nonzero-word count, writes out, resets the counter
// (-> deterministic across graph replays). No second kernel: R3 showed the tiny
// reduce launch alone cost 4.9us of the 8.7us total.

static constexpr int B = 128;
static constexpr int L = 4096;
static constexpr int O = 10;
static constexpr int W = 5;
static constexpr int OW = O * W;          // 50
static constexpr int S = 4;               // segments per batch row
static constexpr int SEG = L / S;         // 1024 elements per segment
static constexpr int THREADS = 256;       // SEG/4 vectors -> 1 int4 per thread
static constexpr int TSIZE = 2048;        // hash slots (power of 2), load ~0.024
static constexpr int KEMPTY = (int)0x80000000;  // impossible key (values in [0, 50000))

__device__ float        g_partial[B * S * O];  // per-(batch,segment) partial sums
__device__ unsigned int g_done[B];             // arrival counters (zero-init; reset after use)

__device__ __forceinline__ unsigned hash_key(int key) {
    return ((unsigned)key * 2654435761u) >> (32 - 11);   // top 11 bits -> [0,2048)
}

__global__ __launch_bounds__(THREADS)
void oas_kernel(const int* __restrict__ doc_idx,
                const float* __restrict__ doc_prob,
                const int* __restrict__ options,
                float* __restrict__ out) {
    __shared__ int   s_key[TSIZE];
    __shared__ float s_acc[TSIZE];
    __shared__ int   s_last;

    const int bx  = blockIdx.x;
    const int b   = bx >> 2;        // batch
    const int seg = bx & (S - 1);   // segment within the row
    const int tid = threadIdx.x;

    // ---- prefetch this thread's doc data FIRST: DRAM latency hides behind table setup ----
    const int base = b * L + seg * SEG;
    const int4   d4 = reinterpret_cast<const int4*>(doc_idx + base)[tid];
    const float4 p4 = reinterpret_cast<const float4*>(doc_prob + base)[tid];

    // ---- init table ----
    #pragma unroll
    for (int i = tid; i < TSIZE; i += THREADS) {
        s_key[i] = KEMPTY;
        s_acc[i] = 0.0f;
    }
    __syncthreads();

    // ---- insert the (<=50) option words ----
    const int* opt = options + b * OW;
    if (tid < OW) {
        const int key = opt[tid];
        unsigned h = hash_key(key);
        while (true) {
            int old = atomicCAS(&s_key[h], KEMPTY, key);
            if (old == KEMPTY || old == key) break;
            h = (h + 1) & (TSIZE - 1);
        }
    }
    __syncthreads();

    // ---- probe: batch the 4 first-probe LDS (independent) before branching ----
    const int   dk[4] = {d4.x, d4.y, d4.z, d4.w};
    const float pp[4] = {p4.x, p4.y, p4.z, p4.w};

    unsigned hh[4];
    int      k0[4];
    #pragma unroll
    for (int j = 0; j < 4; j++) hh[j] = hash_key(dk[j]);
    #pragma unroll
    for (int j = 0; j < 4; j++) k0[j] = s_key[hh[j]];

    #pragma unroll
    for (int j = 0; j < 4; j++) {
        if (k0[j] == dk[j]) {
            atomicAdd(&s_acc[hh[j]], pp[j]);      // hit on first probe
        } else if (k0[j] != KEMPTY) {             // rare: collided slot, walk the cluster
            unsigned h = (hh[j] + 1) & (TSIZE - 1);
            while (true) {
                const int k = s_key[h];
                if (k == KEMPTY) break;
                if (k == dk[j]) { atomicAdd(&s_acc[h], pp[j]); break; }
                h = (h + 1) & (TSIZE - 1);
            }
        }
        // k0 == KEMPTY: miss, nothing to do (~95.9% of elements)
    }
    __syncthreads();

    // ---- per-option partial sums for this segment ----
    if (tid < O) {
        float sum = 0.0f;
        #pragma unroll
        for (int w = 0; w < W; w++) {
            const int key = opt[tid * W + w];
            unsigned h = hash_key(key);
            while (s_key[h] != key) h = (h + 1) & (TSIZE - 1);  // guaranteed present
            sum += s_acc[h];
        }
        g_partial[(b * S + seg) * O + tid] = sum;
        __threadfence();                          // make partials visible device-wide
    }
    __syncthreads();

    // ---- last CTA of this batch reduces and writes the output row ----
    if (tid == 0) {
        const unsigned prev = atomicAdd(&g_done[b], 1u);
        s_last = (prev == S - 1) ? 1 : 0;
    }
    __syncthreads();

    if (s_last) {
        if (tid == 0) {
            g_done[b] = 0;                        // reset for next graph replay
            __threadfence();
        }
        if (tid < O) {
            float sum = 0.0f;
            #pragma unroll
            for (int s = 0; s < S; s++) {
                sum += g_partial[(b * S + s) * O + tid];
            }
            float cnt = 0.0f;
            #pragma unroll
            for (int w = 0; w < W; w++) {
                if (opt[tid * W + w] != 0) cnt += 1.0f;
            }
            out[b * O + tid] = sum / cnt;
        }
    }
}

extern "C" void kernel_launch(void* const* d_in, const int* in_sizes, int n_in,
                              void* d_out, int out_size) {
    const int*   doc_idx  = (const int*)d_in[0];     // (B, L) int32 (JAX-downgraded int64)
    const float* doc_prob = (const float*)d_in[1];   // (B, L) float32
    const int*   options  = (const int*)d_in[2];     // (B, O, W) int32
    float*       out      = (float*)d_out;           // (B, O) float32

    oas_kernel<<<B * S, THREADS>>>(doc_idx, doc_prob, options, out);
}

// round 7
// speedup vs baseline: 1.4638x; 1.4638x over previous
#include <cuda_runtime.h>
#include <cuda_bf16.h>
#include <cstdint>

// OptionAttentionSum: out[b,o] = (sum_w sum_l [doc[b,l]==opt[b,o,w]] * prob[b,l]) / #nonzero words
//
// R5: single launch, zero cross-CTA traffic. One CTA per batch row, 1024 threads:
// each thread owns exactly one int4 of doc indices + one float4 of probs. 2048-slot
// hash table (load 0.024 -> first probe hits ~98% of occupied slots; ~96% of doc
// words miss on an EMPTY first slot -> near-branchless). Doc loads issued before
// table init so DRAM latency hides behind smem setup. Plain stores to out.
// R4 post-mortem: threadfence(+CCTL.IVALL L1 flush) + counter atomics per CTA cost
// +6us -- all cross-CTA sync machinery removed.

static constexpr int B = 128;
static constexpr int L = 4096;
static constexpr int O = 10;
static constexpr int W = 5;
static constexpr int OW = O * W;          // 50
static constexpr int THREADS = 1024;      // L/4 -> one int4 per thread
static constexpr int TSIZE = 2048;        // hash slots (power of 2), load ~0.024
static constexpr int KEMPTY = (int)0x80000000;  // impossible key (values in [0, 50000))

__device__ __forceinline__ unsigned hash_key(int key) {
    return ((unsigned)key * 2654435761u) >> (32 - 11);   // top 11 bits -> [0,2048)
}

__global__ __launch_bounds__(THREADS, 1)
void oas_kernel(const int* __restrict__ doc_idx,
                const float* __restrict__ doc_prob,
                const int* __restrict__ options,
                float* __restrict__ out) {
    __shared__ int   s_key[TSIZE];
    __shared__ float s_acc[TSIZE];

    const int b   = blockIdx.x;
    const int tid = threadIdx.x;

    // ---- issue this thread's doc loads FIRST: DRAM latency hides behind table setup ----
    const int4   d4 = reinterpret_cast<const int4*>(doc_idx  + b * L)[tid];
    const float4 p4 = reinterpret_cast<const float4*>(doc_prob + b * L)[tid];

    // ---- init table: 2 slots per thread ----
    s_key[tid]           = KEMPTY;
    s_key[tid + THREADS] = KEMPTY;
    s_acc[tid]           = 0.0f;
    s_acc[tid + THREADS] = 0.0f;
    __syncthreads();

    // ---- insert the (<=50) option words ----
    const int* opt = options + b * OW;
    if (tid < OW) {
        const int key = opt[tid];
        unsigned h = hash_key(key);
        while (true) {
            int old = atomicCAS(&s_key[h], KEMPTY, key);
            if (old == KEMPTY || old == key) break;
            h = (h + 1) & (TSIZE - 1);
        }
    }
    __syncthreads();

    // ---- probe: 4 independent first-probe LDS before any branching ----
    const int   dk[4] = {d4.x, d4.y, d4.z, d4.w};
    const float pp[4] = {p4.x, p4.y, p4.z, p4.w};

    unsigned hh[4];
    int      k0[4];
    #pragma unroll
    for (int j = 0; j < 4; j++) hh[j] = hash_key(dk[j]);
    #pragma unroll
    for (int j = 0; j < 4; j++) k0[j] = s_key[hh[j]];

    #pragma unroll
    for (int j = 0; j < 4; j++) {
        if (k0[j] == dk[j]) {
            atomicAdd(&s_acc[hh[j]], pp[j]);      // hit on first probe
        } else if (k0[j] != KEMPTY) {             // rare: collided slot, walk the cluster
            unsigned h = (hh[j] + 1) & (TSIZE - 1);
            while (true) {
                const int k = s_key[h];
                if (k == KEMPTY) break;
                if (k == dk[j]) { atomicAdd(&s_acc[h], pp[j]); break; }
                h = (h + 1) & (TSIZE - 1);
            }
        }
        // k0 == KEMPTY: miss, nothing to do (~96% of elements)
    }
    __syncthreads();

    // ---- epilogue: 10 threads, one option each; plain stores, no cross-CTA sync ----
    if (tid < O) {
        float sum = 0.0f;
        float cnt = 0.0f;
        #pragma unroll
        for (int w = 0; w < W; w++) {
            const int key = opt[tid * W + w];
            unsigned h = hash_key(key);
            while (s_key[h] != key) h = (h + 1) & (TSIZE - 1);  // guaranteed present
            sum += s_acc[h];
            if (key != 0) cnt += 1.0f;
        }
        out[b * O + tid] = sum / cnt;
    }
}

extern "C" void kernel_launch(void* const* d_in, const int* in_sizes, int n_in,
                              void* d_out, int out_size) {
    const int*   doc_idx  = (const int*)d_in[0];     // (B, L) int32 (JAX-downgraded int64)
    const float* doc_prob = (const float*)d_in[1];   // (B, L) float32
    const int*   options  = (const int*)d_in[2];     // (B, O, W) int32
    float*       out      = (float*)d_out;           // (B, O) float32

    oas_kernel<<<B, THREADS>>>(doc_idx, doc_prob, options, out);
}